// round 10
// baseline (speedup 1.0000x reference)
#include <cuda_runtime.h>
#include <cuda_fp16.h>
#include <cstdint>

// Problem constants
#define Ecfg   2048
#define Hcfg   16
#define Dcfg   128
#define Bcfg   4
#define Ncfg   2048
#define QKVN   (Ecfg + 2 * Dcfg)   // 2304
#define Mrows  (Bcfg * Ncfg)       // 8192
#define GK     2048                // K of both GEMMs

// Scratch — all fp16 payloads are PLAIN row-major half pairs (u32 = half2)
__device__ float    g_qkv[(size_t)Mrows * QKVN];
__device__ uint32_t g_xp[(size_t)Mrows * Ecfg / 2];
__device__ uint32_t g_wqkvp[(size_t)QKVN * Ecfg / 2];
__device__ uint32_t g_wfcp[(size_t)Ecfg * Ecfg / 2];
__device__ uint32_t g_kp[(size_t)Mrows * Dcfg / 2];
__device__ uint32_t g_vtp[(size_t)Bcfg * Dcfg * Ncfg / 2];
__device__ uint32_t g_attnp[(size_t)Mrows * Ecfg / 2];

// ---------------------------------------------------------------------------
// helpers
// ---------------------------------------------------------------------------
__device__ __forceinline__ uint32_t h2(float lo, float hi) {
    __half2 h = __floats2half2_rn(lo, hi);
    return *(uint32_t*)&h;
}
__device__ __forceinline__ float ex2(float x) {
    float y;
    asm("ex2.approx.ftz.f32 %0, %1;" : "=f"(y) : "f"(x));
    return y;
}
__device__ __forceinline__ void mma_h(float* d, const uint32_t* a, const uint32_t* b) {
    asm volatile(
        "mma.sync.aligned.m16n8k16.row.col.f32.f16.f16.f32 "
        "{%0,%1,%2,%3}, {%4,%5,%6,%7}, {%8,%9}, {%0,%1,%2,%3};\n"
        : "+f"(d[0]), "+f"(d[1]), "+f"(d[2]), "+f"(d[3])
        : "r"(a[0]), "r"(a[1]), "r"(a[2]), "r"(a[3]), "r"(b[0]), "r"(b[1]));
}
__device__ __forceinline__ uint32_t smem_u32(const void* p) {
    uint32_t a;
    asm("{ .reg .u64 t; cvta.to.shared.u64 t, %1; cvt.u32.u64 %0, t; }" : "=r"(a) : "l"(p));
    return a;
}
#define LDSM4(r, addr) \
    asm volatile("ldmatrix.sync.aligned.m8n8.x4.shared.b16 {%0,%1,%2,%3}, [%4];" \
        : "=r"((r)[0]), "=r"((r)[1]), "=r"((r)[2]), "=r"((r)[3]) : "r"(addr))
#define CP_ASYNC16(sa, gp) \
    asm volatile("cp.async.cg.shared.global [%0], [%1], 16;" :: "r"(sa), "l"(gp))
#define CP_COMMIT() asm volatile("cp.async.commit_group;" ::: "memory")
#define CP_WAIT(n)  asm volatile("cp.async.wait_group %0;" :: "n"(n) : "memory")

// ---------------------------------------------------------------------------
// prep 1: flat fp32 -> plain fp16 pairs (16 floats -> 8 u32)
// ---------------------------------------------------------------------------
__global__ __launch_bounds__(256) void pack_f16_flat(
    const float* __restrict__ src, uint32_t* __restrict__ dst, size_t n16)
{
    size_t t = (size_t)blockIdx.x * 256 + threadIdx.x;
    if (t >= n16) return;
    const float4* s = (const float4*)(src + t * 16);
    float4 a = s[0], b = s[1], c = s[2], d = s[3];
    uint4 o0 = { h2(a.x, a.y), h2(a.z, a.w), h2(b.x, b.y), h2(b.z, b.w) };
    uint4 o1 = { h2(c.x, c.y), h2(c.z, c.w), h2(d.x, d.y), h2(d.z, d.w) };
    uint4* o = (uint4*)(dst + t * 8);
    o[0] = o0; o[1] = o1;
}

// ---------------------------------------------------------------------------
// prep 2: K slice of qkv -> plain fp16 [8192][64 u32]
// ---------------------------------------------------------------------------
__global__ __launch_bounds__(256) void pack_k_kernel(
    const float* __restrict__ qkv, uint32_t* __restrict__ kp)
{
    int t = blockIdx.x * 256 + threadIdx.x;       // 8192*8
    int row = t >> 3, grp = t & 7;
    const float4* s = (const float4*)(qkv + (size_t)row * QKVN + Ecfg + grp * 16);
    float4 a = s[0], b = s[1], c = s[2], d = s[3];
    uint4 o0 = { h2(a.x, a.y), h2(a.z, a.w), h2(b.x, b.y), h2(b.z, b.w) };
    uint4 o1 = { h2(c.x, c.y), h2(c.z, c.w), h2(d.x, d.y), h2(d.z, d.w) };
    uint4* o = (uint4*)(kp + (size_t)row * (Dcfg / 2) + grp * 8);
    o[0] = o0; o[1] = o1;
}

// ---------------------------------------------------------------------------
// prep 3: transpose + fp16: dst[j][i pairs] = src[i][j]
// ---------------------------------------------------------------------------
__global__ __launch_bounds__(256) void transpose_pack(
    const float* __restrict__ src, size_t sStride, size_t zsrc,
    uint32_t* __restrict__ dst, size_t zdst, int NIu)
{
    __shared__ float t[32][33];
    src += (size_t)blockIdx.z * zsrc;
    dst += (size_t)blockIdx.z * zdst;
    const int i0 = blockIdx.x * 32, j0 = blockIdx.y * 32;
    const int tid = threadIdx.x;
#pragma unroll
    for (int s = 0; s < 4; s++) {
        int ii = (tid >> 5) + s * 8, jj = tid & 31;
        t[ii][jj] = src[(size_t)(i0 + ii) * sStride + j0 + jj];
    }
    __syncthreads();
    if (tid < 64) {
        int jj = tid >> 1, grp = tid & 1;
        float v[16];
#pragma unroll
        for (int u = 0; u < 16; u++) v[u] = t[grp * 16 + u][jj];
        uint4 o0 = { h2(v[0], v[1]), h2(v[2], v[3]), h2(v[4], v[5]), h2(v[6], v[7]) };
        uint4 o1 = { h2(v[8], v[9]), h2(v[10], v[11]), h2(v[12], v[13]), h2(v[14], v[15]) };
        uint4* o = (uint4*)(dst + (size_t)(j0 + jj) * NIu + i0 / 2 + grp * 8);
        o[0] = o0; o[1] = o1;
    }
}

// ---------------------------------------------------------------------------
// fp16 GEMM, ldmatrix + 4-stage cp.async, one barrier/chunk.
// BM=128, BN=256, BK=32; 512 threads / 16 warps (4m x 4n), warp tile 32x64.
// smem row padded to 20 u32 -> conflict-free LDSM; 123KB smem, 1 CTA/SM
// (same 16 warps/SM as before, but 25% less L2 traffic).
// ---------------------------------------------------------------------------
#define LDR    20
#define ASTGu  (128 * LDR)                 // 2560 u32 (A region)
#define STGu2  (384 * LDR)                 // 7680 u32 / stage (A+B)
#define NSTG   4
#define GEMM_SMEM (NSTG * STGu2 * 4)       // 122880 B

__global__ __launch_bounds__(512, 1) void gemm_tc(
    const uint32_t* __restrict__ A, const uint32_t* __restrict__ W,
    const float* __restrict__ bias, float* __restrict__ C,
    int Ncols)
{
    extern __shared__ uint32_t sm[];
    const uint32_t sbase = smem_u32(sm);

    const int tid = threadIdx.x;
    const int lane = tid & 31;
    const int wid = tid >> 5;
    const int warp_m = wid & 3;             // 4 warps over 128 rows
    const int warp_n = wid >> 2;            // 4 warps over 256 cols
    const int g = lane >> 2;
    const int tg = lane & 3;
    const int bm = blockIdx.y * 128;
    const int bn = blockIdx.x * 256;

    const int c_r = tid >> 2;               // 0..127
    const int c_c = (tid & 3) * 4;          // u32 chunk col

    const uint32_t* asrc = A + (size_t)(bm + c_r) * (GK / 2) + c_c;
    const uint32_t* bsrc = W + (size_t)(bn + c_r) * (GK / 2) + c_c;

    // ldmatrix lane address bases (bytes)
    const int lr = lane & 7, lb1 = (lane >> 3) & 1, lb2 = (lane >> 4) & 1;
    const uint32_t a_base = sbase + (((warp_m * 32 + lr + lb1 * 8) * LDR) + lb2 * 4) * 4;
    const uint32_t b_base = sbase + ((ASTGu + (warp_n * 64 + lr + lb2 * 8) * LDR) + lb1 * 4) * 4;

    float acc[2][8][4];
#pragma unroll
    for (int mt = 0; mt < 2; mt++)
#pragma unroll
        for (int nt = 0; nt < 8; nt++)
#pragma unroll
            for (int j = 0; j < 4; j++) acc[mt][nt][j] = 0.f;

#define CPA_CHUNK(buf, k0) do { \
    const uint32_t so = sbase + (uint32_t)(buf) * (STGu2 * 4); \
    CP_ASYNC16(so + ((c_r * LDR) + c_c) * 4, asrc + ((k0) >> 1)); \
    _Pragma("unroll") for (int s = 0; s < 2; s++) \
        CP_ASYNC16(so + ((ASTGu + (c_r + 128 * s) * LDR + c_c) * 4), \
                   bsrc + (size_t)(128 * s) * (GK / 2) + ((k0) >> 1)); \
    CP_COMMIT(); \
    } while (0)

#define MMA_CHUNK(buf) do { \
    const uint32_t ab = a_base + (buf) * (STGu2 * 4); \
    const uint32_t bb = b_base + (buf) * (STGu2 * 4); \
    _Pragma("unroll") for (int ks = 0; ks < 2; ks++) { \
        uint32_t a0[4], a1[4]; \
        LDSM4(a0, ab + (ks * 8) * 4); \
        LDSM4(a1, ab + (320 + ks * 8) * 4); \
        _Pragma("unroll") for (int p = 0; p < 4; p++) { \
            uint32_t bq[4]; \
            LDSM4(bq, bb + (p * 320 + ks * 8) * 4); \
            mma_h(acc[0][2 * p],     a0, bq); \
            mma_h(acc[0][2 * p + 1], a0, bq + 2); \
            mma_h(acc[1][2 * p],     a1, bq); \
            mma_h(acc[1][2 * p + 1], a1, bq + 2); } \
    } } while (0)

    const int NCHUNK = GK / 32;             // 64
    CPA_CHUNK(0, 0);
    CPA_CHUNK(1, 32);
    CPA_CHUNK(2, 64);

#pragma unroll 4
    for (int c = 0; c < NCHUNK - 3; c++) {
        CP_WAIT(2);
        __syncthreads();
        CPA_CHUNK((c + 3) & 3, (c + 3) * 32);
        MMA_CHUNK(c & 3);
    }
    // tail: chunks NCHUNK-3 .. NCHUNK-1 (all already prefetched)
    CP_WAIT(2); __syncthreads(); MMA_CHUNK((NCHUNK - 3) & 3);
    CP_WAIT(1); __syncthreads(); MMA_CHUNK((NCHUNK - 2) & 3);
    CP_WAIT(0); __syncthreads(); MMA_CHUNK((NCHUNK - 1) & 3);

#pragma unroll
    for (int mt = 0; mt < 2; mt++) {
        const int row0 = bm + warp_m * 32 + mt * 16 + g;
#pragma unroll
        for (int nt = 0; nt < 8; nt++) {
            const int col = bn + warp_n * 64 + nt * 8 + 2 * tg;
            const float bx = __ldg(&bias[col]);
            const float by = __ldg(&bias[col + 1]);
            float2 v0 = { acc[mt][nt][0] + bx, acc[mt][nt][1] + by };
            float2 v1 = { acc[mt][nt][2] + bx, acc[mt][nt][3] + by };
            *(float2*)(C + (size_t)row0 * Ncols + col) = v0;
            *(float2*)(C + (size_t)(row0 + 8) * Ncols + col) = v1;
        }
    }
}

// ---------------------------------------------------------------------------
// Flash MQA (fp16 mma + ldmatrix). FQ=128, FKV=64; K double-buffered with
// compile-time slot (kb unrolled by 2); V prefetch overlaps S-phase.
// smem 104KB -> 2 CTAs/SM.
// ---------------------------------------------------------------------------
#define FQ     128
#define FKV    64
#define LDQK   68        // u32 row stride for Q/K (64 data + 4 pad)
#define LDVP   36        // u32 row stride for V^T / P (32 data + 4 pad)
#define OFF_Q  0
#define OFF_K  (FQ * LDQK)                        // 8704
#define OFF_V  (OFF_K + 2 * FKV * LDQK)           // 17408
#define OFF_P  (OFF_V + Dcfg * LDVP)              // 22016
#define FLASH_SMEM ((OFF_P + FQ * LDVP) * 4)      // 106496 B

__global__ __launch_bounds__(256, 2) void flash_h(
    const float* __restrict__ qkv, const uint32_t* __restrict__ kp,
    const uint32_t* __restrict__ vtp, uint32_t* __restrict__ outp)
{
    extern __shared__ uint32_t smf[];
    const uint32_t sbase = smem_u32(smf);
    uint32_t* Qs = smf + OFF_Q;

    const int tid = threadIdx.x;
    const int lane = tid & 31;
    const int wid = tid >> 5;
    const int g = lane >> 2;
    const int tg = lane & 3;

    const int qb = (gridDim.x - 1) - blockIdx.x;   // heavy blocks first
    const int h = blockIdx.y;
    const int b = blockIdx.z;
    const int q0 = qb * FQ;

    const float* qbase = qkv + (size_t)b * Ncfg * QKVN + h * Dcfg;
    const uint32_t* kpb = kp + (size_t)b * Ncfg * (Dcfg / 2);
    const uint32_t* vtb = vtp + (size_t)b * Dcfg * (Ncfg / 2);

    const float S2 = 0.08838834764831845f * 1.4426950408889634f;
    const float NEG = -1e30f;

    // Stage Q: fp32 -> fp16 pairs, plain layout
#pragma unroll
    for (int s = 0; s < 16; s++) {
        const int idx = s * 256 + tid;
        const int r = idx >> 5, c4 = (idx & 31) * 4;
        float4 v = *(const float4*)(qbase + (size_t)(q0 + r) * QKVN + c4);
        uint32_t* q = Qs + r * LDQK + (c4 >> 1);
        q[0] = h2(v.x, v.y);
        q[1] = h2(v.z, v.w);
    }

    // ldmatrix lane bases (bytes)
    const int lr = lane & 7, lb1 = (lane >> 3) & 1, lb2 = (lane >> 4) & 1;
    const uint32_t q_base  = sbase + (((16 * wid + lr + lb1 * 8) * LDQK) + lb2 * 4) * 4;
    const uint32_t k_base  = sbase + ((OFF_K + (lr + lb2 * 8) * LDQK) + lb1 * 4) * 4;
    const uint32_t v_base  = sbase + ((OFF_V + (lr + lb2 * 8) * LDVP) + lb1 * 4) * 4;
    const uint32_t pa_base = sbase + ((OFF_P + (16 * wid + lr + lb1 * 8) * LDVP) + lb2 * 4) * 4;
    uint32_t* Ps = smf + OFF_P;

    // FULL tile loads: K = 64 rows x 64 u32 (16KB), V = 128 rows x 32 u32 (16KB)
#define STAGE_K(slot_, k0) do { \
    _Pragma("unroll") for (int s = 0; s < 4; s++) { \
        const int idx = s * 256 + tid; \
        const int r = idx >> 4, c = (idx & 15) * 4; \
        CP_ASYNC16(sbase + (OFF_K + (slot_) * (FKV * LDQK) + r * LDQK + c) * 4, \
                   kpb + (size_t)((k0) + r) * (Dcfg / 2) + c); } \
    CP_COMMIT(); } while (0)

#define STAGE_V(k0) do { \
    _Pragma("unroll") for (int s = 0; s < 4; s++) { \
        const int idx = s * 256 + tid; \
        const int r = idx >> 3, c = (idx & 7) * 4; \
        CP_ASYNC16(sbase + (OFF_V + r * LDVP + c) * 4, \
                   vtb + (size_t)r * (Ncfg / 2) + ((k0) >> 1) + c); } \
    CP_COMMIT(); } while (0)

    float ofr[16][4];
#pragma unroll
    for (int nt = 0; nt < 16; nt++)
#pragma unroll
        for (int j = 0; j < 4; j++) ofr[nt][j] = 0.f;
    float m0 = NEG, m1 = NEG, l0 = 0.f, l1 = 0.f;

    const int wrow = 16 * wid + g;
    const int row0 = q0 + wrow;
    const int row1 = row0 + 8;
    const int nkv = 2 * (qb + 1);

    STAGE_K(0, 0);

#define FLASH_BODY(kb, SLOT) do { \
    __syncthreads(); \
    STAGE_V((kb) * FKV); \
    CP_WAIT(1); \
    __syncthreads(); \
    float sfr[8][4]; \
    _Pragma("unroll") for (int nt = 0; nt < 8; nt++) \
        _Pragma("unroll") for (int j = 0; j < 4; j++) sfr[nt][j] = 0.f; \
    _Pragma("unroll") for (int ks = 0; ks < 8; ks++) { \
        uint32_t aq[4]; \
        LDSM4(aq, q_base + ks * 32); \
        _Pragma("unroll") for (int p = 0; p < 4; p++) { \
            uint32_t bq[4]; \
            LDSM4(bq, k_base + ((SLOT) * (FKV * LDQK) + p * 16 * LDQK + ks * 8) * 4); \
            mma_h(sfr[2 * p],     aq, bq); \
            mma_h(sfr[2 * p + 1], aq, bq + 2); } \
    } \
    _Pragma("unroll") for (int nt = 0; nt < 8; nt++) \
        _Pragma("unroll") for (int j = 0; j < 4; j++) sfr[nt][j] *= S2; \
    const int k0m = (kb) * FKV; \
    if ((kb) >= nkv - 2) { \
        _Pragma("unroll") for (int nt = 0; nt < 8; nt++) { \
            const int c0 = k0m + 8 * nt + 2 * tg; \
            if (c0     > row0) sfr[nt][0] = NEG; \
            if (c0 + 1 > row0) sfr[nt][1] = NEG; \
            if (c0     > row1) sfr[nt][2] = NEG; \
            if (c0 + 1 > row1) sfr[nt][3] = NEG; } \
    } \
    float mx0 = NEG, mx1 = NEG; \
    _Pragma("unroll") for (int nt = 0; nt < 8; nt++) { \
        mx0 = fmaxf(mx0, fmaxf(sfr[nt][0], sfr[nt][1])); \
        mx1 = fmaxf(mx1, fmaxf(sfr[nt][2], sfr[nt][3])); } \
    mx0 = fmaxf(mx0, __shfl_xor_sync(0xffffffff, mx0, 1)); \
    mx0 = fmaxf(mx0, __shfl_xor_sync(0xffffffff, mx0, 2)); \
    mx1 = fmaxf(mx1, __shfl_xor_sync(0xffffffff, mx1, 1)); \
    mx1 = fmaxf(mx1, __shfl_xor_sync(0xffffffff, mx1, 2)); \
    const float mn0 = fmaxf(m0, mx0); \
    const float mn1 = fmaxf(m1, mx1); \
    const float scl0 = ex2(m0 - mn0); \
    const float scl1 = ex2(m1 - mn1); \
    float sum0 = 0.f, sum1 = 0.f; \
    _Pragma("unroll") for (int nt = 0; nt < 8; nt++) { \
        sfr[nt][0] = ex2(sfr[nt][0] - mn0); \
        sfr[nt][1] = ex2(sfr[nt][1] - mn0); \
        sfr[nt][2] = ex2(sfr[nt][2] - mn1); \
        sfr[nt][3] = ex2(sfr[nt][3] - mn1); \
        sum0 += sfr[nt][0] + sfr[nt][1]; \
        sum1 += sfr[nt][2] + sfr[nt][3]; } \
    sum0 += __shfl_xor_sync(0xffffffff, sum0, 1); \
    sum0 += __shfl_xor_sync(0xffffffff, sum0, 2); \
    sum1 += __shfl_xor_sync(0xffffffff, sum1, 1); \
    sum1 += __shfl_xor_sync(0xffffffff, sum1, 2); \
    l0 = l0 * scl0 + sum0;  m0 = mn0; \
    l1 = l1 * scl1 + sum1;  m1 = mn1; \
    if ((kb) + 1 < nkv) STAGE_K((SLOT) ^ 1, ((kb) + 1) * FKV); \
    _Pragma("unroll") for (int nt = 0; nt < 8; nt++) { \
        Ps[(wrow)     * LDVP + 4 * nt + tg] = h2(sfr[nt][0], sfr[nt][1]); \
        Ps[(wrow + 8) * LDVP + 4 * nt + tg] = h2(sfr[nt][2], sfr[nt][3]); } \
    _Pragma("unroll") for (int nt = 0; nt < 16; nt++) { \
        ofr[nt][0] *= scl0; ofr[nt][1] *= scl0; \
        ofr[nt][2] *= scl1; ofr[nt][3] *= scl1; } \
    if ((kb) + 1 < nkv) { CP_WAIT(1); } else { CP_WAIT(0); } \
    __syncthreads(); \
    _Pragma("unroll") for (int ks = 0; ks < 4; ks++) { \
        uint32_t ap[4]; \
        LDSM4(ap, pa_base + ks * 32); \
        _Pragma("unroll") for (int p = 0; p < 8; p++) { \
            uint32_t bv[4]; \
            LDSM4(bv, v_base + (p * 16 * LDVP + ks * 8) * 4); \
            mma_h(ofr[2 * p],     ap, bv); \
            mma_h(ofr[2 * p + 1], ap, bv + 2); } \
    } } while (0)

    for (int kb2 = 0; kb2 < nkv; kb2 += 2) {
        FLASH_BODY(kb2, 0);
        FLASH_BODY(kb2 + 1, 1);
    }

    // epilogue: plain fp16 pairs
    const float rl0 = 1.f / l0;
    const float rl1 = 1.f / l1;
    uint32_t* o0 = outp + (size_t)(b * Ncfg + row0) * (Ecfg / 2) + h * (Dcfg / 2);
    uint32_t* o1 = outp + (size_t)(b * Ncfg + row1) * (Ecfg / 2) + h * (Dcfg / 2);
#pragma unroll
    for (int nt = 0; nt < 16; nt++) {
        o0[4 * nt + tg] = h2(ofr[nt][0] * rl0, ofr[nt][1] * rl0);
        o1[4 * nt + tg] = h2(ofr[nt][2] * rl1, ofr[nt][3] * rl1);
    }
}

// ---------------------------------------------------------------------------
extern "C" void kernel_launch(void* const* d_in, const int* in_sizes, int n_in,
                              void* d_out, int out_size)
{
    const float* x     = (const float*)d_in[0];
    const float* w_qkv = (const float*)d_in[1];
    const float* b_qkv = (const float*)d_in[2];
    const float* w_fc  = (const float*)d_in[3];
    const float* b_fc  = (const float*)d_in[4];
    float* out = (float*)d_out;

    float* qkv_ptr;  uint32_t *xp, *wqkvp, *wfcp, *kpp, *vtpp, *attnp;
    cudaGetSymbolAddress((void**)&qkv_ptr, g_qkv);
    cudaGetSymbolAddress((void**)&xp, g_xp);
    cudaGetSymbolAddress((void**)&wqkvp, g_wqkvp);
    cudaGetSymbolAddress((void**)&wfcp, g_wfcp);
    cudaGetSymbolAddress((void**)&kpp, g_kp);
    cudaGetSymbolAddress((void**)&vtpp, g_vtp);
    cudaGetSymbolAddress((void**)&attnp, g_attnp);

    cudaFuncSetAttribute(gemm_tc, cudaFuncAttributeMaxDynamicSharedMemorySize, GEMM_SMEM);
    cudaFuncSetAttribute(flash_h, cudaFuncAttributeMaxDynamicSharedMemorySize, FLASH_SMEM);

    // 0) pack x; transpose weights (fp16)
    pack_f16_flat<<<(Mrows * Ecfg / 16 + 255) / 256, 256>>>(x, xp, (size_t)Mrows * Ecfg / 16);
    transpose_pack<<<dim3(Ecfg / 32, QKVN / 32, 1), 256>>>(w_qkv, QKVN, 0, wqkvp, 0, Ecfg / 2);
    transpose_pack<<<dim3(Ecfg / 32, Ecfg / 32, 1), 256>>>(w_fc, Ecfg, 0, wfcp, 0, Ecfg / 2);

    // 1) qkv = x @ w_qkv + b_qkv   (BN=256: 9 x 64 grid)
    gemm_tc<<<dim3(QKVN / 256, Mrows / 128), 512, GEMM_SMEM>>>(
        xp, wqkvp, b_qkv, qkv_ptr, QKVN);

    // 2) pack K; transpose V^T
    pack_k_kernel<<<Mrows * 8 / 256, 256>>>(qkv_ptr, kpp);
    transpose_pack<<<dim3(Ncfg / 32, Dcfg / 32, Bcfg), 256>>>(
        qkv_ptr + Ecfg + Dcfg, QKVN, (size_t)Ncfg * QKVN, vtpp, (size_t)Dcfg * Ncfg / 2, Ncfg / 2);

    // 3) flash attention -> fp16 attn
    flash_h<<<dim3(Ncfg / FQ, Hcfg, Bcfg), 256, FLASH_SMEM>>>(
        qkv_ptr, kpp, vtpp, attnp);

    // 4) out = attn @ w_fc + b_fc   (8 x 64 grid)
    gemm_tc<<<dim3(Ecfg / 256, Mrows / 128), 512, GEMM_SMEM>>>(
        attnp, wfcp, b_fc, out, Ecfg);
}

// round 11
// speedup vs baseline: 1.0530x; 1.0530x over previous
#include <cuda_runtime.h>
#include <cuda_fp16.h>
#include <cstdint>

// Problem constants
#define Ecfg   2048
#define Hcfg   16
#define Dcfg   128
#define Bcfg   4
#define Ncfg   2048
#define QKVN   (Ecfg + 2 * Dcfg)   // 2304
#define Mrows  (Bcfg * Ncfg)       // 8192
#define GK     2048                // K of both GEMMs

// Scratch — all fp16 payloads are PLAIN row-major half pairs (u32 = half2)
__device__ float    g_qkv[(size_t)Mrows * QKVN];
__device__ uint32_t g_xp[(size_t)Mrows * Ecfg / 2];
__device__ uint32_t g_wqkvp[(size_t)QKVN * Ecfg / 2];
__device__ uint32_t g_wfcp[(size_t)Ecfg * Ecfg / 2];
__device__ uint32_t g_kp[(size_t)Mrows * Dcfg / 2];
__device__ uint32_t g_vtp[(size_t)Bcfg * Dcfg * Ncfg / 2];
__device__ uint32_t g_attnp[(size_t)Mrows * Ecfg / 2];

// ---------------------------------------------------------------------------
// helpers
// ---------------------------------------------------------------------------
__device__ __forceinline__ uint32_t h2(float lo, float hi) {
    __half2 h = __floats2half2_rn(lo, hi);
    return *(uint32_t*)&h;
}
__device__ __forceinline__ float ex2(float x) {
    float y;
    asm("ex2.approx.ftz.f32 %0, %1;" : "=f"(y) : "f"(x));
    return y;
}
__device__ __forceinline__ void mma_h(float* d, const uint32_t* a, const uint32_t* b) {
    asm volatile(
        "mma.sync.aligned.m16n8k16.row.col.f32.f16.f16.f32 "
        "{%0,%1,%2,%3}, {%4,%5,%6,%7}, {%8,%9}, {%0,%1,%2,%3};\n"
        : "+f"(d[0]), "+f"(d[1]), "+f"(d[2]), "+f"(d[3])
        : "r"(a[0]), "r"(a[1]), "r"(a[2]), "r"(a[3]), "r"(b[0]), "r"(b[1]));
}
__device__ __forceinline__ uint32_t smem_u32(const void* p) {
    uint32_t a;
    asm("{ .reg .u64 t; cvta.to.shared.u64 t, %1; cvt.u32.u64 %0, t; }" : "=r"(a) : "l"(p));
    return a;
}
#define LDSM4(r, addr) \
    asm volatile("ldmatrix.sync.aligned.m8n8.x4.shared.b16 {%0,%1,%2,%3}, [%4];" \
        : "=r"((r)[0]), "=r"((r)[1]), "=r"((r)[2]), "=r"((r)[3]) : "r"(addr))
#define CP_ASYNC16(sa, gp) \
    asm volatile("cp.async.cg.shared.global [%0], [%1], 16;" :: "r"(sa), "l"(gp))
#define CP_COMMIT() asm volatile("cp.async.commit_group;" ::: "memory")
#define CP_WAIT(n)  asm volatile("cp.async.wait_group %0;" :: "n"(n) : "memory")

// ---------------------------------------------------------------------------
// prep 1: flat fp32 -> plain fp16 pairs (16 floats -> 8 u32)
// ---------------------------------------------------------------------------
__global__ __launch_bounds__(256) void pack_f16_flat(
    const float* __restrict__ src, uint32_t* __restrict__ dst, size_t n16)
{
    size_t t = (size_t)blockIdx.x * 256 + threadIdx.x;
    if (t >= n16) return;
    const float4* s = (const float4*)(src + t * 16);
    float4 a = s[0], b = s[1], c = s[2], d = s[3];
    uint4 o0 = { h2(a.x, a.y), h2(a.z, a.w), h2(b.x, b.y), h2(b.z, b.w) };
    uint4 o1 = { h2(c.x, c.y), h2(c.z, c.w), h2(d.x, d.y), h2(d.z, d.w) };
    uint4* o = (uint4*)(dst + t * 8);
    o[0] = o0; o[1] = o1;
}

// ---------------------------------------------------------------------------
// prep 2: transpose + fp16: dst[j][i pairs] = src[i][j]
// ---------------------------------------------------------------------------
__global__ __launch_bounds__(256) void transpose_pack(
    const float* __restrict__ src, size_t sStride, size_t zsrc,
    uint32_t* __restrict__ dst, size_t zdst, int NIu)
{
    __shared__ float t[32][33];
    src += (size_t)blockIdx.z * zsrc;
    dst += (size_t)blockIdx.z * zdst;
    const int i0 = blockIdx.x * 32, j0 = blockIdx.y * 32;
    const int tid = threadIdx.x;
#pragma unroll
    for (int s = 0; s < 4; s++) {
        int ii = (tid >> 5) + s * 8, jj = tid & 31;
        t[ii][jj] = src[(size_t)(i0 + ii) * sStride + j0 + jj];
    }
    __syncthreads();
    if (tid < 64) {
        int jj = tid >> 1, grp = tid & 1;
        float v[16];
#pragma unroll
        for (int u = 0; u < 16; u++) v[u] = t[grp * 16 + u][jj];
        uint4 o0 = { h2(v[0], v[1]), h2(v[2], v[3]), h2(v[4], v[5]), h2(v[6], v[7]) };
        uint4 o1 = { h2(v[8], v[9]), h2(v[10], v[11]), h2(v[12], v[13]), h2(v[14], v[15]) };
        uint4* o = (uint4*)(dst + (size_t)(j0 + jj) * NIu + i0 / 2 + grp * 8);
        o[0] = o0; o[1] = o1;
    }
}

// ---------------------------------------------------------------------------
// fp16 GEMM, ldmatrix + 4-stage cp.async, one barrier/chunk, 2 CTAs/SM.
// BM=128, BN=128, BK=32; warp tile 32x64 (round-9 proven config).
// kv_fuse: for gemm1, col-block 16 (= K slice) is emitted as packed fp16 rows
// into kp_out, col-block 17 (= V slice) as fp16 V^T halves into vt_out;
// fp32 stores skipped for those blocks.
// ---------------------------------------------------------------------------
#define LDR    20
#define HSTGu  (128 * LDR)                 // 2560 u32
#define STGu2  (2 * HSTGu)                 // 5120 u32 / stage
#define NSTG   4
#define GEMM_SMEM (NSTG * STGu2 * 4)       // 81920 B

__global__ __launch_bounds__(256, 2) void gemm_tc(
    const uint32_t* __restrict__ A, const uint32_t* __restrict__ W,
    const float* __restrict__ bias, float* __restrict__ C,
    int Ncols, int kv_fuse,
    uint32_t* __restrict__ kp_out, uint32_t* __restrict__ vt_out)
{
    extern __shared__ uint32_t sm[];
    const uint32_t sbase = smem_u32(sm);

    const int tid = threadIdx.x;
    const int lane = tid & 31;
    const int wid = tid >> 5;
    const int warp_m = wid & 3;
    const int warp_n = wid >> 2;
    const int g = lane >> 2;
    const int tg = lane & 3;
    const int bm = blockIdx.y * 128;
    const int bn = blockIdx.x * 128;

    const int c_r = tid >> 2;               // 0..63 (+64)
    const int c_c = (tid & 3) * 4;          // u32 chunk col

    const uint32_t* asrc = A + (size_t)(bm + c_r) * (GK / 2) + c_c;
    const uint32_t* bsrc = W + (size_t)(bn + c_r) * (GK / 2) + c_c;

    // ldmatrix lane address bases (bytes)
    const int lr = lane & 7, lb1 = (lane >> 3) & 1, lb2 = (lane >> 4) & 1;
    const uint32_t a_base = sbase + (((warp_m * 32 + lr + lb1 * 8) * LDR) + lb2 * 4) * 4;
    const uint32_t b_base = sbase + ((HSTGu + (warp_n * 64 + lr + lb2 * 8) * LDR) + lb1 * 4) * 4;

    float acc[2][8][4];
#pragma unroll
    for (int mt = 0; mt < 2; mt++)
#pragma unroll
        for (int nt = 0; nt < 8; nt++)
#pragma unroll
            for (int j = 0; j < 4; j++) acc[mt][nt][j] = 0.f;

#define CPA_CHUNK(buf, k0) do { \
    const uint32_t so = sbase + (uint32_t)(buf) * (STGu2 * 4); \
    _Pragma("unroll") for (int s = 0; s < 2; s++) \
        CP_ASYNC16(so + (((c_r + 64 * s) * LDR) + c_c) * 4, \
                   asrc + (size_t)(64 * s) * (GK / 2) + ((k0) >> 1)); \
    _Pragma("unroll") for (int s = 0; s < 2; s++) \
        CP_ASYNC16(so + ((HSTGu + (c_r + 64 * s) * LDR + c_c) * 4), \
                   bsrc + (size_t)(64 * s) * (GK / 2) + ((k0) >> 1)); \
    CP_COMMIT(); \
    } while (0)

#define MMA_CHUNK(buf) do { \
    const uint32_t ab = a_base + (buf) * (STGu2 * 4); \
    const uint32_t bb = b_base + (buf) * (STGu2 * 4); \
    _Pragma("unroll") for (int ks = 0; ks < 2; ks++) { \
        uint32_t a0[4], a1[4]; \
        LDSM4(a0, ab + (ks * 8) * 4); \
        LDSM4(a1, ab + (320 + ks * 8) * 4); \
        _Pragma("unroll") for (int p = 0; p < 4; p++) { \
            uint32_t bq[4]; \
            LDSM4(bq, bb + (p * 320 + ks * 8) * 4); \
            mma_h(acc[0][2 * p],     a0, bq); \
            mma_h(acc[0][2 * p + 1], a0, bq + 2); \
            mma_h(acc[1][2 * p],     a1, bq); \
            mma_h(acc[1][2 * p + 1], a1, bq + 2); } \
    } } while (0)

    const int NCHUNK = GK / 32;             // 64
    CPA_CHUNK(0, 0);
    CPA_CHUNK(1, 32);
    CPA_CHUNK(2, 64);

#pragma unroll 4
    for (int c = 0; c < NCHUNK - 3; c++) {
        CP_WAIT(2);
        __syncthreads();
        CPA_CHUNK((c + 3) & 3, (c + 3) * 32);
        MMA_CHUNK(c & 3);
    }
    CP_WAIT(2); __syncthreads(); MMA_CHUNK((NCHUNK - 3) & 3);
    CP_WAIT(1); __syncthreads(); MMA_CHUNK((NCHUNK - 2) & 3);
    CP_WAIT(0); __syncthreads(); MMA_CHUNK((NCHUNK - 1) & 3);

    const int kvblk = (kv_fuse && bn >= Ecfg) ? (bn == Ecfg ? 1 : 2) : 0;

#pragma unroll
    for (int mt = 0; mt < 2; mt++) {
        const int row0 = bm + warp_m * 32 + mt * 16 + g;
#pragma unroll
        for (int nt = 0; nt < 8; nt++) {
            const int col = bn + warp_n * 64 + nt * 8 + 2 * tg;
            const float bx = __ldg(&bias[col]);
            const float by = __ldg(&bias[col + 1]);
            float2 v0 = { acc[mt][nt][0] + bx, acc[mt][nt][1] + by };
            float2 v1 = { acc[mt][nt][2] + bx, acc[mt][nt][3] + by };
            if (kvblk == 0) {
                *(float2*)(C + (size_t)row0 * Ncols + col) = v0;
                *(float2*)(C + (size_t)(row0 + 8) * Ncols + col) = v1;
            } else if (kvblk == 1) {
                // K slice: packed fp16 rows [row][64 u32]
                const int cu = (col - Ecfg) >> 1;
                kp_out[(size_t)row0 * (Dcfg / 2) + cu]       = h2(v0.x, v0.y);
                kp_out[(size_t)(row0 + 8) * (Dcfg / 2) + cu] = h2(v1.x, v1.y);
            } else {
                // V slice: V^T halves [b][d][n]
                __half* vth = (__half*)vt_out;
                const int d0 = col - (Ecfg + Dcfg);
                const int b_ = row0 >> 11, nloc = row0 & 2047;
                const size_t base0 = (((size_t)(b_ * Dcfg + d0)) << 11) + nloc;
                vth[base0]              = __float2half_rn(v0.x);
                vth[base0 + (1 << 11)]  = __float2half_rn(v0.y);
                vth[base0 + 8]             = __float2half_rn(v1.x);
                vth[base0 + (1 << 11) + 8] = __float2half_rn(v1.y);
            }
        }
    }
}

// ---------------------------------------------------------------------------
// Flash MQA (fp16 mma + ldmatrix). FQ=128, FKV=64; K double-buffered with
// compile-time slot (kb unrolled by 2); V prefetch overlaps S-phase.
// Main loop maskless; last 2 KV blocks masked. smem 104KB -> 2 CTAs/SM.
// ---------------------------------------------------------------------------
#define FQ     128
#define FKV    64
#define LDQK   68
#define LDVP   36
#define OFF_Q  0
#define OFF_K  (FQ * LDQK)                        // 8704
#define OFF_V  (OFF_K + 2 * FKV * LDQK)           // 17408
#define OFF_P  (OFF_V + Dcfg * LDVP)              // 22016
#define FLASH_SMEM ((OFF_P + FQ * LDVP) * 4)      // 106496 B

__global__ __launch_bounds__(256, 2) void flash_h(
    const float* __restrict__ qkv, const uint32_t* __restrict__ kp,
    const uint32_t* __restrict__ vtp, uint32_t* __restrict__ outp)
{
    extern __shared__ uint32_t smf[];
    const uint32_t sbase = smem_u32(smf);
    uint32_t* Qs = smf + OFF_Q;

    const int tid = threadIdx.x;
    const int lane = tid & 31;
    const int wid = tid >> 5;
    const int g = lane >> 2;
    const int tg = lane & 3;

    const int qb = (gridDim.x - 1) - blockIdx.x;   // heavy blocks first
    const int h = blockIdx.y;
    const int b = blockIdx.z;
    const int q0 = qb * FQ;

    const float* qbase = qkv + (size_t)b * Ncfg * QKVN + h * Dcfg;
    const uint32_t* kpb = kp + (size_t)b * Ncfg * (Dcfg / 2);
    const uint32_t* vtb = vtp + (size_t)b * Dcfg * (Ncfg / 2);

    const float S2 = 0.08838834764831845f * 1.4426950408889634f;
    const float NEG = -1e30f;

    // Stage Q: fp32 -> fp16 pairs
#pragma unroll
    for (int s = 0; s < 16; s++) {
        const int idx = s * 256 + tid;
        const int r = idx >> 5, c4 = (idx & 31) * 4;
        float4 v = *(const float4*)(qbase + (size_t)(q0 + r) * QKVN + c4);
        uint32_t* q = Qs + r * LDQK + (c4 >> 1);
        q[0] = h2(v.x, v.y);
        q[1] = h2(v.z, v.w);
    }

    const int lr = lane & 7, lb1 = (lane >> 3) & 1, lb2 = (lane >> 4) & 1;
    const uint32_t q_base  = sbase + (((16 * wid + lr + lb1 * 8) * LDQK) + lb2 * 4) * 4;
    const uint32_t k_base  = sbase + ((OFF_K + (lr + lb2 * 8) * LDQK) + lb1 * 4) * 4;
    const uint32_t v_base  = sbase + ((OFF_V + (lr + lb2 * 8) * LDVP) + lb1 * 4) * 4;
    const uint32_t pa_base = sbase + ((OFF_P + (16 * wid + lr + lb1 * 8) * LDVP) + lb2 * 4) * 4;
    uint32_t* Ps = smf + OFF_P;

#define STAGE_K(slot_, k0) do { \
    _Pragma("unroll") for (int s = 0; s < 4; s++) { \
        const int idx = s * 256 + tid; \
        const int r = idx >> 4, c = (idx & 15) * 4; \
        CP_ASYNC16(sbase + (OFF_K + (slot_) * (FKV * LDQK) + r * LDQK + c) * 4, \
                   kpb + (size_t)((k0) + r) * (Dcfg / 2) + c); } \
    CP_COMMIT(); } while (0)

#define STAGE_V(k0) do { \
    _Pragma("unroll") for (int s = 0; s < 4; s++) { \
        const int idx = s * 256 + tid; \
        const int r = idx >> 3, c = (idx & 7) * 4; \
        CP_ASYNC16(sbase + (OFF_V + r * LDVP + c) * 4, \
                   vtb + (size_t)r * (Ncfg / 2) + ((k0) >> 1) + c); } \
    CP_COMMIT(); } while (0)

    float ofr[16][4];
#pragma unroll
    for (int nt = 0; nt < 16; nt++)
#pragma unroll
        for (int j = 0; j < 4; j++) ofr[nt][j] = 0.f;
    float m0 = NEG, m1 = NEG, l0 = 0.f, l1 = 0.f;

    const int wrow = 16 * wid + g;
    const int row0 = q0 + wrow;
    const int row1 = row0 + 8;
    const int nkv = 2 * (qb + 1);

    STAGE_K(0, 0);

#define FLASH_BODY(kb, SLOT, MASKED) do { \
    __syncthreads(); \
    STAGE_V((kb) * FKV); \
    CP_WAIT(1); \
    __syncthreads(); \
    float sfr[8][4]; \
    _Pragma("unroll") for (int nt = 0; nt < 8; nt++) \
        _Pragma("unroll") for (int j = 0; j < 4; j++) sfr[nt][j] = 0.f; \
    _Pragma("unroll") for (int ks = 0; ks < 8; ks++) { \
        uint32_t aq[4]; \
        LDSM4(aq, q_base + ks * 32); \
        _Pragma("unroll") for (int p = 0; p < 4; p++) { \
            uint32_t bq[4]; \
            LDSM4(bq, k_base + ((SLOT) * (FKV * LDQK) + p * 16 * LDQK + ks * 8) * 4); \
            mma_h(sfr[2 * p],     aq, bq); \
            mma_h(sfr[2 * p + 1], aq, bq + 2); } \
    } \
    _Pragma("unroll") for (int nt = 0; nt < 8; nt++) \
        _Pragma("unroll") for (int j = 0; j < 4; j++) sfr[nt][j] *= S2; \
    if (MASKED) { \
        const int k0m = (kb) * FKV; \
        _Pragma("unroll") for (int nt = 0; nt < 8; nt++) { \
            const int c0 = k0m + 8 * nt + 2 * tg; \
            if (c0     > row0) sfr[nt][0] = NEG; \
            if (c0 + 1 > row0) sfr[nt][1] = NEG; \
            if (c0     > row1) sfr[nt][2] = NEG; \
            if (c0 + 1 > row1) sfr[nt][3] = NEG; } \
    } \
    float mx0 = NEG, mx1 = NEG; \
    _Pragma("unroll") for (int nt = 0; nt < 8; nt++) { \
        mx0 = fmaxf(mx0, fmaxf(sfr[nt][0], sfr[nt][1])); \
        mx1 = fmaxf(mx1, fmaxf(sfr[nt][2], sfr[nt][3])); } \
    mx0 = fmaxf(mx0, __shfl_xor_sync(0xffffffff, mx0, 1)); \
    mx0 = fmaxf(mx0, __shfl_xor_sync(0xffffffff, mx0, 2)); \
    mx1 = fmaxf(mx1, __shfl_xor_sync(0xffffffff, mx1, 1)); \
    mx1 = fmaxf(mx1, __shfl_xor_sync(0xffffffff, mx1, 2)); \
    const float mn0 = fmaxf(m0, mx0); \
    const float mn1 = fmaxf(m1, mx1); \
    const float scl0 = ex2(m0 - mn0); \
    const float scl1 = ex2(m1 - mn1); \
    float sum0 = 0.f, sum1 = 0.f; \
    _Pragma("unroll") for (int nt = 0; nt < 8; nt++) { \
        sfr[nt][0] = ex2(sfr[nt][0] - mn0); \
        sfr[nt][1] = ex2(sfr[nt][1] - mn0); \
        sfr[nt][2] = ex2(sfr[nt][2] - mn1); \
        sfr[nt][3] = ex2(sfr[nt][3] - mn1); \
        sum0 += sfr[nt][0] + sfr[nt][1]; \
        sum1 += sfr[nt][2] + sfr[nt][3]; } \
    sum0 += __shfl_xor_sync(0xffffffff, sum0, 1); \
    sum0 += __shfl_xor_sync(0xffffffff, sum0, 2); \
    sum1 += __shfl_xor_sync(0xffffffff, sum1, 1); \
    sum1 += __shfl_xor_sync(0xffffffff, sum1, 2); \
    l0 = l0 * scl0 + sum0;  m0 = mn0; \
    l1 = l1 * scl1 + sum1;  m1 = mn1; \
    if ((kb) + 1 < nkv) STAGE_K((SLOT) ^ 1, ((kb) + 1) * FKV); \
    _Pragma("unroll") for (int nt = 0; nt < 8; nt++) { \
        Ps[(wrow)     * LDVP + 4 * nt + tg] = h2(sfr[nt][0], sfr[nt][1]); \
        Ps[(wrow + 8) * LDVP + 4 * nt + tg] = h2(sfr[nt][2], sfr[nt][3]); } \
    _Pragma("unroll") for (int nt = 0; nt < 16; nt++) { \
        ofr[nt][0] *= scl0; ofr[nt][1] *= scl0; \
        ofr[nt][2] *= scl1; ofr[nt][3] *= scl1; } \
    if ((kb) + 1 < nkv) { CP_WAIT(1); } else { CP_WAIT(0); } \
    __syncthreads(); \
    _Pragma("unroll") for (int ks = 0; ks < 4; ks++) { \
        uint32_t ap[4]; \
        LDSM4(ap, pa_base + ks * 32); \
        _Pragma("unroll") for (int p = 0; p < 8; p++) { \
            uint32_t bv[4]; \
            LDSM4(bv, v_base + (p * 16 * LDVP + ks * 8) * 4); \
            mma_h(ofr[2 * p],     ap, bv); \
            mma_h(ofr[2 * p + 1], ap, bv + 2); } \
    } } while (0)

    // maskless main loop, masked 2-block tail (nkv is even, >= 2)
    int kb2 = 0;
    for (; kb2 + 2 < nkv; kb2 += 2) {
        FLASH_BODY(kb2, 0, false);
        FLASH_BODY(kb2 + 1, 1, false);
    }
    FLASH_BODY(kb2, 0, true);
    FLASH_BODY(kb2 + 1, 1, true);

    // epilogue: plain fp16 pairs
    const float rl0 = 1.f / l0;
    const float rl1 = 1.f / l1;
    uint32_t* o0 = outp + (size_t)(b * Ncfg + row0) * (Ecfg / 2) + h * (Dcfg / 2);
    uint32_t* o1 = outp + (size_t)(b * Ncfg + row1) * (Ecfg / 2) + h * (Dcfg / 2);
#pragma unroll
    for (int nt = 0; nt < 16; nt++) {
        o0[4 * nt + tg] = h2(ofr[nt][0] * rl0, ofr[nt][1] * rl0);
        o1[4 * nt + tg] = h2(ofr[nt][2] * rl1, ofr[nt][3] * rl1);
    }
}

// ---------------------------------------------------------------------------
extern "C" void kernel_launch(void* const* d_in, const int* in_sizes, int n_in,
                              void* d_out, int out_size)
{
    const float* x     = (const float*)d_in[0];
    const float* w_qkv = (const float*)d_in[1];
    const float* b_qkv = (const float*)d_in[2];
    const float* w_fc  = (const float*)d_in[3];
    const float* b_fc  = (const float*)d_in[4];
    float* out = (float*)d_out;

    float* qkv_ptr;  uint32_t *xp, *wqkvp, *wfcp, *kpp, *vtpp, *attnp;
    cudaGetSymbolAddress((void**)&qkv_ptr, g_qkv);
    cudaGetSymbolAddress((void**)&xp, g_xp);
    cudaGetSymbolAddress((void**)&wqkvp, g_wqkvp);
    cudaGetSymbolAddress((void**)&wfcp, g_wfcp);
    cudaGetSymbolAddress((void**)&kpp, g_kp);
    cudaGetSymbolAddress((void**)&vtpp, g_vtp);
    cudaGetSymbolAddress((void**)&attnp, g_attnp);

    cudaFuncSetAttribute(gemm_tc, cudaFuncAttributeMaxDynamicSharedMemorySize, GEMM_SMEM);
    cudaFuncSetAttribute(flash_h, cudaFuncAttributeMaxDynamicSharedMemorySize, FLASH_SMEM);

    // 0) pack x; transpose weights (fp16)
    pack_f16_flat<<<(Mrows * Ecfg / 16 + 255) / 256, 256>>>(x, xp, (size_t)Mrows * Ecfg / 16);
    transpose_pack<<<dim3(Ecfg / 32, QKVN / 32, 1), 256>>>(w_qkv, QKVN, 0, wqkvp, 0, Ecfg / 2);
    transpose_pack<<<dim3(Ecfg / 32, Ecfg / 32, 1), 256>>>(w_fc, Ecfg, 0, wfcp, 0, Ecfg / 2);

    // 1) qkv = x @ w_qkv + b_qkv; K/V emitted directly as fp16 (kv_fuse)
    gemm_tc<<<dim3(QKVN / 128, Mrows / 128), 256, GEMM_SMEM>>>(
        xp, wqkvp, b_qkv, qkv_ptr, QKVN, 1, kpp, vtpp);

    // 2) flash attention -> fp16 attn
    flash_h<<<dim3(Ncfg / FQ, Hcfg, Bcfg), 256, FLASH_SMEM>>>(
        qkv_ptr, kpp, vtpp, attnp);

    // 3) out = attn @ w_fc + b_fc
    gemm_tc<<<dim3(Ecfg / 128, Mrows / 128), 256, GEMM_SMEM>>>(
        attnp, wfcp, b_fc, out, Ecfg, 0, nullptr, nullptr);
}

// round 12
// speedup vs baseline: 1.0741x; 1.0201x over previous
#include <cuda_runtime.h>
#include <cuda_fp16.h>
#include <cstdint>

// Problem constants
#define Ecfg   2048
#define Hcfg   16
#define Dcfg   128
#define Bcfg   4
#define Ncfg   2048
#define QKVN   (Ecfg + 2 * Dcfg)   // 2304
#define Mrows  (Bcfg * Ncfg)       // 8192
#define GK     2048                // K of both GEMMs

// Scratch — all fp16 payloads are PLAIN row-major half pairs (u32 = half2)
__device__ float    g_qkv[(size_t)Mrows * QKVN];
__device__ uint32_t g_xp[(size_t)Mrows * Ecfg / 2];
__device__ uint32_t g_wqkvp[(size_t)QKVN * Ecfg / 2];
__device__ uint32_t g_wfcp[(size_t)Ecfg * Ecfg / 2];
__device__ uint32_t g_kp[(size_t)Mrows * Dcfg / 2];
__device__ uint32_t g_vtp[(size_t)Bcfg * Dcfg * Ncfg / 2];
__device__ uint32_t g_attnp[(size_t)Mrows * Ecfg / 2];

// ---------------------------------------------------------------------------
// helpers
// ---------------------------------------------------------------------------
__device__ __forceinline__ uint32_t h2(float lo, float hi) {
    __half2 h = __floats2half2_rn(lo, hi);
    return *(uint32_t*)&h;
}
__device__ __forceinline__ float ex2(float x) {
    float y;
    asm("ex2.approx.ftz.f32 %0, %1;" : "=f"(y) : "f"(x));
    return y;
}
__device__ __forceinline__ void mma_h(float* d, const uint32_t* a, const uint32_t* b) {
    asm volatile(
        "mma.sync.aligned.m16n8k16.row.col.f32.f16.f16.f32 "
        "{%0,%1,%2,%3}, {%4,%5,%6,%7}, {%8,%9}, {%0,%1,%2,%3};\n"
        : "+f"(d[0]), "+f"(d[1]), "+f"(d[2]), "+f"(d[3])
        : "r"(a[0]), "r"(a[1]), "r"(a[2]), "r"(a[3]), "r"(b[0]), "r"(b[1]));
}
__device__ __forceinline__ uint32_t smem_u32(const void* p) {
    uint32_t a;
    asm("{ .reg .u64 t; cvta.to.shared.u64 t, %1; cvt.u32.u64 %0, t; }" : "=r"(a) : "l"(p));
    return a;
}
#define LDSM4(r, addr) \
    asm volatile("ldmatrix.sync.aligned.m8n8.x4.shared.b16 {%0,%1,%2,%3}, [%4];" \
        : "=r"((r)[0]), "=r"((r)[1]), "=r"((r)[2]), "=r"((r)[3]) : "r"(addr))
#define CP_ASYNC16(sa, gp) \
    asm volatile("cp.async.cg.shared.global [%0], [%1], 16;" :: "r"(sa), "l"(gp))
#define CP_COMMIT() asm volatile("cp.async.commit_group;" ::: "memory")
#define CP_WAIT(n)  asm volatile("cp.async.wait_group %0;" :: "n"(n) : "memory")

// ---------------------------------------------------------------------------
// prep 1: flat fp32 -> plain fp16 pairs (16 floats -> 8 u32)
// ---------------------------------------------------------------------------
__global__ __launch_bounds__(256) void pack_f16_flat(
    const float* __restrict__ src, uint32_t* __restrict__ dst, size_t n16)
{
    size_t t = (size_t)blockIdx.x * 256 + threadIdx.x;
    if (t >= n16) return;
    const float4* s = (const float4*)(src + t * 16);
    float4 a = s[0], b = s[1], c = s[2], d = s[3];
    uint4 o0 = { h2(a.x, a.y), h2(a.z, a.w), h2(b.x, b.y), h2(b.z, b.w) };
    uint4 o1 = { h2(c.x, c.y), h2(c.z, c.w), h2(d.x, d.y), h2(d.z, d.w) };
    uint4* o = (uint4*)(dst + t * 8);
    o[0] = o0; o[1] = o1;
}

// ---------------------------------------------------------------------------
// prep 2: transpose + fp16: dst[j][i pairs] = src[i][j]
// ---------------------------------------------------------------------------
__global__ __launch_bounds__(256) void transpose_pack(
    const float* __restrict__ src, size_t sStride, size_t zsrc,
    uint32_t* __restrict__ dst, size_t zdst, int NIu)
{
    __shared__ float t[32][33];
    src += (size_t)blockIdx.z * zsrc;
    dst += (size_t)blockIdx.z * zdst;
    const int i0 = blockIdx.x * 32, j0 = blockIdx.y * 32;
    const int tid = threadIdx.x;
#pragma unroll
    for (int s = 0; s < 4; s++) {
        int ii = (tid >> 5) + s * 8, jj = tid & 31;
        t[ii][jj] = src[(size_t)(i0 + ii) * sStride + j0 + jj];
    }
    __syncthreads();
    if (tid < 64) {
        int jj = tid >> 1, grp = tid & 1;
        float v[16];
#pragma unroll
        for (int u = 0; u < 16; u++) v[u] = t[grp * 16 + u][jj];
        uint4 o0 = { h2(v[0], v[1]), h2(v[2], v[3]), h2(v[4], v[5]), h2(v[6], v[7]) };
        uint4 o1 = { h2(v[8], v[9]), h2(v[10], v[11]), h2(v[12], v[13]), h2(v[14], v[15]) };
        uint4* o = (uint4*)(dst + (size_t)(j0 + jj) * NIu + i0 / 2 + grp * 8);
        o[0] = o0; o[1] = o1;
    }
}

// ---------------------------------------------------------------------------
// fp16 GEMM, ldmatrix + 4-stage cp.async, one barrier/chunk, 2 CTAs/SM.
// BM=128, BN=128, BK=32; 128 threads / 4 WARPS, warp tile 64x64.
// Halved LDSM traffic vs 8-warp version (32KB/chunk vs 48KB).
// ---------------------------------------------------------------------------
#define LDR    20
#define HSTGu  (128 * LDR)                 // 2560 u32
#define STGu2  (2 * HSTGu)                 // 5120 u32 / stage
#define NSTG   4
#define GEMM_SMEM (NSTG * STGu2 * 4)       // 81920 B

__global__ __launch_bounds__(128, 2) void gemm_tc(
    const uint32_t* __restrict__ A, const uint32_t* __restrict__ W,
    const float* __restrict__ bias, float* __restrict__ C,
    int Ncols, int kv_fuse,
    uint32_t* __restrict__ kp_out, uint32_t* __restrict__ vt_out)
{
    extern __shared__ uint32_t sm[];
    const uint32_t sbase = smem_u32(sm);

    const int tid = threadIdx.x;
    const int lane = tid & 31;
    const int wid = tid >> 5;               // 0..3
    const int warp_m = wid & 1;             // 2 warps over M (64 rows each)
    const int warp_n = wid >> 1;            // 2 warps over N (64 cols each)
    const int g = lane >> 2;
    const int tg = lane & 3;
    const int bm = blockIdx.y * 128;
    const int bn = blockIdx.x * 128;

    const int c_r = tid >> 2;               // 0..31 (+32*s)
    const int c_c = (tid & 3) * 4;

    const uint32_t* asrc = A + (size_t)(bm + c_r) * (GK / 2) + c_c;
    const uint32_t* bsrc = W + (size_t)(bn + c_r) * (GK / 2) + c_c;

    // ldmatrix lane address bases (bytes)
    const int lnr = lane & 7, lb1 = (lane >> 3) & 1, lb2 = (lane >> 4) & 1;
    const uint32_t a_base = sbase + (((warp_m * 64 + lnr + lb1 * 8) * LDR) + lb2 * 4) * 4;
    const uint32_t b_base = sbase + ((HSTGu + (warp_n * 64 + lnr + lb2 * 8) * LDR) + lb1 * 4) * 4;

    float acc[4][8][4];
#pragma unroll
    for (int mt = 0; mt < 4; mt++)
#pragma unroll
        for (int nt = 0; nt < 8; nt++)
#pragma unroll
            for (int j = 0; j < 4; j++) acc[mt][nt][j] = 0.f;

#define CPA_CHUNK(buf, k0) do { \
    const uint32_t so = sbase + (uint32_t)(buf) * (STGu2 * 4); \
    _Pragma("unroll") for (int s = 0; s < 4; s++) \
        CP_ASYNC16(so + (((c_r + 32 * s) * LDR) + c_c) * 4, \
                   asrc + (size_t)(32 * s) * (GK / 2) + ((k0) >> 1)); \
    _Pragma("unroll") for (int s = 0; s < 4; s++) \
        CP_ASYNC16(so + ((HSTGu + (c_r + 32 * s) * LDR + c_c) * 4), \
                   bsrc + (size_t)(32 * s) * (GK / 2) + ((k0) >> 1)); \
    CP_COMMIT(); \
    } while (0)

#define MMA_CHUNK(buf) do { \
    const uint32_t ab = a_base + (buf) * (STGu2 * 4); \
    const uint32_t bb = b_base + (buf) * (STGu2 * 4); \
    _Pragma("unroll") for (int ks = 0; ks < 2; ks++) { \
        uint32_t af[4][4]; \
        _Pragma("unroll") for (int mt = 0; mt < 4; mt++) \
            LDSM4(af[mt], ab + mt * 1280 + ks * 32); \
        _Pragma("unroll") for (int p = 0; p < 4; p++) { \
            uint32_t bq[4]; \
            LDSM4(bq, bb + (p * 320 + ks * 8) * 4); \
            _Pragma("unroll") for (int mt = 0; mt < 4; mt++) { \
                mma_h(acc[mt][2 * p],     af[mt], bq); \
                mma_h(acc[mt][2 * p + 1], af[mt], bq + 2); } } \
    } } while (0)

    const int NCHUNK = GK / 32;             // 64
    CPA_CHUNK(0, 0);
    CPA_CHUNK(1, 32);
    CPA_CHUNK(2, 64);

#pragma unroll 4
    for (int c = 0; c < NCHUNK - 3; c++) {
        CP_WAIT(2);
        __syncthreads();
        CPA_CHUNK((c + 3) & 3, (c + 3) * 32);
        MMA_CHUNK(c & 3);
    }
    CP_WAIT(2); __syncthreads(); MMA_CHUNK((NCHUNK - 3) & 3);
    CP_WAIT(1); __syncthreads(); MMA_CHUNK((NCHUNK - 2) & 3);
    CP_WAIT(0); __syncthreads(); MMA_CHUNK((NCHUNK - 1) & 3);

    const int kvblk = (kv_fuse && bn >= Ecfg) ? (bn == Ecfg ? 1 : 2) : 0;

#pragma unroll
    for (int mt = 0; mt < 4; mt++) {
        const int row0 = bm + warp_m * 64 + mt * 16 + g;
#pragma unroll
        for (int nt = 0; nt < 8; nt++) {
            const int col = bn + warp_n * 64 + nt * 8 + 2 * tg;
            const float bx = __ldg(&bias[col]);
            const float by = __ldg(&bias[col + 1]);
            float2 v0 = { acc[mt][nt][0] + bx, acc[mt][nt][1] + by };
            float2 v1 = { acc[mt][nt][2] + bx, acc[mt][nt][3] + by };
            if (kvblk == 0) {
                *(float2*)(C + (size_t)row0 * Ncols + col) = v0;
                *(float2*)(C + (size_t)(row0 + 8) * Ncols + col) = v1;
            } else if (kvblk == 1) {
                const int cu = (col - Ecfg) >> 1;
                kp_out[(size_t)row0 * (Dcfg / 2) + cu]       = h2(v0.x, v0.y);
                kp_out[(size_t)(row0 + 8) * (Dcfg / 2) + cu] = h2(v1.x, v1.y);
            } else {
                __half* vth = (__half*)vt_out;
                const int d0 = col - (Ecfg + Dcfg);
                const int b_ = row0 >> 11, nloc = row0 & 2047;
                const size_t base0 = (((size_t)(b_ * Dcfg + d0)) << 11) + nloc;
                vth[base0]              = __float2half_rn(v0.x);
                vth[base0 + (1 << 11)]  = __float2half_rn(v0.y);
                vth[base0 + 8]             = __float2half_rn(v1.x);
                vth[base0 + (1 << 11) + 8] = __float2half_rn(v1.y);
            }
        }
    }
}

// ---------------------------------------------------------------------------
// Flash MQA (fp16 mma + ldmatrix). FQ=128, 128 threads / 4 WARPS,
// warp tile 32 Q rows x 64 KV (halved K/V fragment redundancy).
// FKV=64; K double-buffered; V prefetch overlaps S-phase; maskless main loop.
// smem 104KB -> 2 CTAs/SM. regs capped at 255 (128 thr).
// ---------------------------------------------------------------------------
#define FQ     128
#define FKV    64
#define LDQK   68
#define LDVP   36
#define OFF_Q  0
#define OFF_K  (FQ * LDQK)                        // 8704
#define OFF_V  (OFF_K + 2 * FKV * LDQK)           // 17408
#define OFF_P  (OFF_V + Dcfg * LDVP)              // 22016
#define FLASH_SMEM ((OFF_P + FQ * LDVP) * 4)      // 106496 B

__global__ __launch_bounds__(128, 2) void flash_h(
    const float* __restrict__ qkv, const uint32_t* __restrict__ kp,
    const uint32_t* __restrict__ vtp, uint32_t* __restrict__ outp)
{
    extern __shared__ uint32_t smf[];
    const uint32_t sbase = smem_u32(smf);
    uint32_t* Qs = smf + OFF_Q;

    const int tid = threadIdx.x;
    const int lane = tid & 31;
    const int wid = tid >> 5;               // 0..3, each owns 32 Q rows
    const int g = lane >> 2;
    const int tg = lane & 3;

    const int qb = (gridDim.x - 1) - blockIdx.x;   // heavy blocks first
    const int h = blockIdx.y;
    const int b = blockIdx.z;
    const int q0 = qb * FQ;

    const float* qbase = qkv + (size_t)b * Ncfg * QKVN + h * Dcfg;
    const uint32_t* kpb = kp + (size_t)b * Ncfg * (Dcfg / 2);
    const uint32_t* vtb = vtp + (size_t)b * Dcfg * (Ncfg / 2);

    const float S2 = 0.08838834764831845f * 1.4426950408889634f;
    const float NEG = -1e30f;

    // Stage Q: fp32 -> fp16 pairs (128 rows x 64 u32)
#pragma unroll
    for (int s = 0; s < 32; s++) {
        const int idx = s * 128 + tid;
        const int r = idx >> 5, c4 = (idx & 31) * 4;
        float4 v = *(const float4*)(qbase + (size_t)(q0 + r) * QKVN + c4);
        uint32_t* q = Qs + r * LDQK + (c4 >> 1);
        q[0] = h2(v.x, v.y);
        q[1] = h2(v.z, v.w);
    }

    const int lnr = lane & 7, lb1 = (lane >> 3) & 1, lb2 = (lane >> 4) & 1;
    const uint32_t q_base  = sbase + (((32 * wid + lnr + lb1 * 8) * LDQK) + lb2 * 4) * 4;
    const uint32_t k_base  = sbase + ((OFF_K + (lnr + lb2 * 8) * LDQK) + lb1 * 4) * 4;
    const uint32_t v_base  = sbase + ((OFF_V + (lnr + lb2 * 8) * LDVP) + lb1 * 4) * 4;
    const uint32_t pa_base = sbase + ((OFF_P + (32 * wid + lnr + lb1 * 8) * LDVP) + lb2 * 4) * 4;
    uint32_t* Ps = smf + OFF_P;

    // FULL tile loads: K = 64 rows x 64 u32 (16KB), V = 128 rows x 32 u32 (16KB)
#define STAGE_K(slot_, k0) do { \
    _Pragma("unroll") for (int s = 0; s < 8; s++) { \
        const int idx = s * 128 + tid; \
        const int r = idx >> 4, c = (idx & 15) * 4; \
        CP_ASYNC16(sbase + (OFF_K + (slot_) * (FKV * LDQK) + r * LDQK + c) * 4, \
                   kpb + (size_t)((k0) + r) * (Dcfg / 2) + c); } \
    CP_COMMIT(); } while (0)

#define STAGE_V(k0) do { \
    _Pragma("unroll") for (int s = 0; s < 8; s++) { \
        const int idx = s * 128 + tid; \
        const int r = idx >> 3, c = (idx & 7) * 4; \
        CP_ASYNC16(sbase + (OFF_V + r * LDVP + c) * 4, \
                   vtb + (size_t)r * (Ncfg / 2) + ((k0) >> 1) + c); } \
    CP_COMMIT(); } while (0)

    float ofr[2][16][4];
#pragma unroll
    for (int mt = 0; mt < 2; mt++)
#pragma unroll
        for (int nt = 0; nt < 16; nt++)
#pragma unroll
            for (int j = 0; j < 4; j++) ofr[mt][nt][j] = 0.f;
    float mS[2][2] = { {NEG, NEG}, {NEG, NEG} };
    float lS[2][2] = { {0.f, 0.f}, {0.f, 0.f} };

    const int wrow = 32 * wid + g;           // mt=0 first row (local)
    const int nkv = 2 * (qb + 1);

    STAGE_K(0, 0);

#define FLASH_BODY(kb, SLOT, MASKED) do { \
    __syncthreads(); \
    STAGE_V((kb) * FKV); \
    CP_WAIT(1); \
    __syncthreads(); \
    float sfr[2][8][4]; \
    _Pragma("unroll") for (int mt = 0; mt < 2; mt++) \
        _Pragma("unroll") for (int nt = 0; nt < 8; nt++) \
            _Pragma("unroll") for (int j = 0; j < 4; j++) sfr[mt][nt][j] = 0.f; \
    _Pragma("unroll") for (int ks = 0; ks < 8; ks++) { \
        uint32_t aq0[4], aq1[4]; \
        LDSM4(aq0, q_base + ks * 32); \
        LDSM4(aq1, q_base + 16 * LDQK * 4 + ks * 32); \
        _Pragma("unroll") for (int p = 0; p < 4; p++) { \
            uint32_t bq[4]; \
            LDSM4(bq, k_base + ((SLOT) * (FKV * LDQK) + p * 16 * LDQK + ks * 8) * 4); \
            mma_h(sfr[0][2 * p],     aq0, bq); \
            mma_h(sfr[0][2 * p + 1], aq0, bq + 2); \
            mma_h(sfr[1][2 * p],     aq1, bq); \
            mma_h(sfr[1][2 * p + 1], aq1, bq + 2); } \
    } \
    _Pragma("unroll") for (int mt = 0; mt < 2; mt++) \
        _Pragma("unroll") for (int nt = 0; nt < 8; nt++) \
            _Pragma("unroll") for (int j = 0; j < 4; j++) sfr[mt][nt][j] *= S2; \
    if (MASKED) { \
        const int k0m = (kb) * FKV; \
        _Pragma("unroll") for (int mt = 0; mt < 2; mt++) { \
            const int rA = q0 + wrow + 16 * mt, rB = rA + 8; \
            _Pragma("unroll") for (int nt = 0; nt < 8; nt++) { \
                const int c0 = k0m + 8 * nt + 2 * tg; \
                if (c0     > rA) sfr[mt][nt][0] = NEG; \
                if (c0 + 1 > rA) sfr[mt][nt][1] = NEG; \
                if (c0     > rB) sfr[mt][nt][2] = NEG; \
                if (c0 + 1 > rB) sfr[mt][nt][3] = NEG; } } \
    } \
    float sclA[2], sclB[2]; \
    _Pragma("unroll") for (int mt = 0; mt < 2; mt++) { \
        float mx0 = NEG, mx1 = NEG; \
        _Pragma("unroll") for (int nt = 0; nt < 8; nt++) { \
            mx0 = fmaxf(mx0, fmaxf(sfr[mt][nt][0], sfr[mt][nt][1])); \
            mx1 = fmaxf(mx1, fmaxf(sfr[mt][nt][2], sfr[mt][nt][3])); } \
        mx0 = fmaxf(mx0, __shfl_xor_sync(0xffffffff, mx0, 1)); \
        mx0 = fmaxf(mx0, __shfl_xor_sync(0xffffffff, mx0, 2)); \
        mx1 = fmaxf(mx1, __shfl_xor_sync(0xffffffff, mx1, 1)); \
        mx1 = fmaxf(mx1, __shfl_xor_sync(0xffffffff, mx1, 2)); \
        const float mn0 = fmaxf(mS[mt][0], mx0); \
        const float mn1 = fmaxf(mS[mt][1], mx1); \
        sclA[mt] = ex2(mS[mt][0] - mn0); \
        sclB[mt] = ex2(mS[mt][1] - mn1); \
        float sum0 = 0.f, sum1 = 0.f; \
        _Pragma("unroll") for (int nt = 0; nt < 8; nt++) { \
            sfr[mt][nt][0] = ex2(sfr[mt][nt][0] - mn0); \
            sfr[mt][nt][1] = ex2(sfr[mt][nt][1] - mn0); \
            sfr[mt][nt][2] = ex2(sfr[mt][nt][2] - mn1); \
            sfr[mt][nt][3] = ex2(sfr[mt][nt][3] - mn1); \
            sum0 += sfr[mt][nt][0] + sfr[mt][nt][1]; \
            sum1 += sfr[mt][nt][2] + sfr[mt][nt][3]; } \
        sum0 += __shfl_xor_sync(0xffffffff, sum0, 1); \
        sum0 += __shfl_xor_sync(0xffffffff, sum0, 2); \
        sum1 += __shfl_xor_sync(0xffffffff, sum1, 1); \
        sum1 += __shfl_xor_sync(0xffffffff, sum1, 2); \
        lS[mt][0] = lS[mt][0] * sclA[mt] + sum0;  mS[mt][0] = mn0; \
        lS[mt][1] = lS[mt][1] * sclB[mt] + sum1;  mS[mt][1] = mn1; } \
    if ((kb) + 1 < nkv) STAGE_K((SLOT) ^ 1, ((kb) + 1) * FKV); \
    _Pragma("unroll") for (int mt = 0; mt < 2; mt++) \
        _Pragma("unroll") for (int nt = 0; nt < 8; nt++) { \
            Ps[(wrow + 16 * mt)     * LDVP + 4 * nt + tg] = h2(sfr[mt][nt][0], sfr[mt][nt][1]); \
            Ps[(wrow + 16 * mt + 8) * LDVP + 4 * nt + tg] = h2(sfr[mt][nt][2], sfr[mt][nt][3]); } \
    _Pragma("unroll") for (int mt = 0; mt < 2; mt++) \
        _Pragma("unroll") for (int nt = 0; nt < 16; nt++) { \
            ofr[mt][nt][0] *= sclA[mt]; ofr[mt][nt][1] *= sclA[mt]; \
            ofr[mt][nt][2] *= sclB[mt]; ofr[mt][nt][3] *= sclB[mt]; } \
    if ((kb) + 1 < nkv) { CP_WAIT(1); } else { CP_WAIT(0); } \
    __syncthreads(); \
    _Pragma("unroll") for (int ks = 0; ks < 4; ks++) { \
        uint32_t ap0[4], ap1[4]; \
        LDSM4(ap0, pa_base + ks * 32); \
        LDSM4(ap1, pa_base + 16 * LDVP * 4 + ks * 32); \
        _Pragma("unroll") for (int p = 0; p < 8; p++) { \
            uint32_t bv[4]; \
            LDSM4(bv, v_base + (p * 16 * LDVP + ks * 8) * 4); \
            mma_h(ofr[0][2 * p],     ap0, bv); \
            mma_h(ofr[0][2 * p + 1], ap0, bv + 2); \
            mma_h(ofr[1][2 * p],     ap1, bv); \
            mma_h(ofr[1][2 * p + 1], ap1, bv + 2); } \
    } } while (0)

    // maskless main loop, masked 2-block tail (nkv is even, >= 2)
    int kb2 = 0;
    for (; kb2 + 2 < nkv; kb2 += 2) {
        FLASH_BODY(kb2, 0, false);
        FLASH_BODY(kb2 + 1, 1, false);
    }
    FLASH_BODY(kb2, 0, true);
    FLASH_BODY(kb2 + 1, 1, true);

    // epilogue: plain fp16 pairs
#pragma unroll
    for (int mt = 0; mt < 2; mt++) {
        const int rA = q0 + wrow + 16 * mt, rB = rA + 8;
        const float rlA = 1.f / lS[mt][0];
        const float rlB = 1.f / lS[mt][1];
        uint32_t* o0 = outp + (size_t)(b * Ncfg + rA) * (Ecfg / 2) + h * (Dcfg / 2);
        uint32_t* o1 = outp + (size_t)(b * Ncfg + rB) * (Ecfg / 2) + h * (Dcfg / 2);
#pragma unroll
        for (int nt = 0; nt < 16; nt++) {
            o0[4 * nt + tg] = h2(ofr[mt][nt][0] * rlA, ofr[mt][nt][1] * rlA);
            o1[4 * nt + tg] = h2(ofr[mt][nt][2] * rlB, ofr[mt][nt][3] * rlB);
        }
    }
}

// ---------------------------------------------------------------------------
extern "C" void kernel_launch(void* const* d_in, const int* in_sizes, int n_in,
                              void* d_out, int out_size)
{
    const float* x     = (const float*)d_in[0];
    const float* w_qkv = (const float*)d_in[1];
    const float* b_qkv = (const float*)d_in[2];
    const float* w_fc  = (const float*)d_in[3];
    const float* b_fc  = (const float*)d_in[4];
    float* out = (float*)d_out;

    float* qkv_ptr;  uint32_t *xp, *wqkvp, *wfcp, *kpp, *vtpp, *attnp;
    cudaGetSymbolAddress((void**)&qkv_ptr, g_qkv);
    cudaGetSymbolAddress((void**)&xp, g_xp);
    cudaGetSymbolAddress((void**)&wqkvp, g_wqkvp);
    cudaGetSymbolAddress((void**)&wfcp, g_wfcp);
    cudaGetSymbolAddress((void**)&kpp, g_kp);
    cudaGetSymbolAddress((void**)&vtpp, g_vtp);
    cudaGetSymbolAddress((void**)&attnp, g_attnp);

    cudaFuncSetAttribute(gemm_tc, cudaFuncAttributeMaxDynamicSharedMemorySize, GEMM_SMEM);
    cudaFuncSetAttribute(flash_h, cudaFuncAttributeMaxDynamicSharedMemorySize, FLASH_SMEM);

    // 0) pack x; transpose weights (fp16)
    pack_f16_flat<<<(Mrows * Ecfg / 16 + 255) / 256, 256>>>(x, xp, (size_t)Mrows * Ecfg / 16);
    transpose_pack<<<dim3(Ecfg / 32, QKVN / 32, 1), 256>>>(w_qkv, QKVN, 0, wqkvp, 0, Ecfg / 2);
    transpose_pack<<<dim3(Ecfg / 32, Ecfg / 32, 1), 256>>>(w_fc, Ecfg, 0, wfcp, 0, Ecfg / 2);

    // 1) qkv = x @ w_qkv + b_qkv; K/V emitted directly as fp16 (kv_fuse)
    gemm_tc<<<dim3(QKVN / 128, Mrows / 128), 128, GEMM_SMEM>>>(
        xp, wqkvp, b_qkv, qkv_ptr, QKVN, 1, kpp, vtpp);

    // 2) flash attention -> fp16 attn
    flash_h<<<dim3(Ncfg / FQ, Hcfg, Bcfg), 128, FLASH_SMEM>>>(
        qkv_ptr, kpp, vtpp, attnp);

    // 3) out = attn @ w_fc + b_fc
    gemm_tc<<<dim3(Ecfg / 128, Mrows / 128), 128, GEMM_SMEM>>>(
        attnp, wfcp, b_fc, out, Ecfg, 0, nullptr, nullptr);
}